// round 3
// baseline (speedup 1.0000x reference)
#include <cuda_runtime.h>
#include <cuda_bf16.h>
#include <cfloat>

// Problem constants (StyleCodebook: B=16, N=4096, D=256, K=512)
static constexpr int TOKENS = 16 * 4096;   // 65536
static constexpr int D      = 256;
static constexpr int D2     = D / 2;       // k-pairs
static constexpr int K      = 512;

// Tiling for the fused distance+argmin kernel
static constexpr int BM = 64;    // tokens per CTA
static constexpr int BN = 128;   // codes per chunk
static constexpr int NCHUNK = K / BN;  // 4
static constexpr int TM = 4;     // tokens per thread
static constexpr int TN = 8;     // codes per thread
// 16x16 thread grid = 256 threads

// smem layout (dynamic): zs2[D2][BM] (u64) | es2[D2][BN] (u64) | esq[K] (f32)
static constexpr size_t ZS_U64   = (size_t)D2 * BM;           // 8192  u64 = 64KB
static constexpr size_t ES_U64   = (size_t)D2 * BN;           // 16384 u64 = 128KB
static constexpr size_t SMEM_BYTES = (ZS_U64 + ES_U64) * 8 + K * 4;  // 198656

// Scratch (device globals; no allocation allowed)
__device__ int   g_indices[TOKENS];
__device__ float g_partial[TOKENS];
__device__ float g_partial2[256];
__device__ float g_esq[K];

// Packed fp32x2 FMA (Blackwell FFMA2 — PTX-only)
#define FMA_F32X2(acc, a, b) \
    asm("fma.rn.f32x2 %0, %1, %2, %3;" : "=l"(acc) : "l"(a), "l"(b), "l"(acc))

// ---------------------------------------------------------------------------
// Kernel 0: codebook row squared norms
// ---------------------------------------------------------------------------
__global__ void esq_kernel(const float* __restrict__ cb) {
    int k = blockIdx.x;        // one block per code
    int d = threadIdx.x;       // D threads
    float v = cb[(size_t)k * D + d];
    float s = v * v;
    #pragma unroll
    for (int o = 16; o > 0; o >>= 1) s += __shfl_down_sync(0xffffffffu, s, o);
    __shared__ float ws[8];
    if ((d & 31) == 0) ws[d >> 5] = s;
    __syncthreads();
    if (d == 0) {
        float tot = 0.f;
        #pragma unroll
        for (int w = 0; w < 8; ++w) tot += ws[w];
        g_esq[k] = tot;
    }
}

// ---------------------------------------------------------------------------
// Kernel 1: fused z @ cb^T with running argmin per token, FFMA2 inner loop.
// Both operands pre-paired over K in smem so fma.rn.f32x2 needs no packing:
//   zs2[k2][m] = (z[2k2][m], z[2k2+1][m]),  es2[k2][c] = (e[2k2][c], e[2k2+1][c])
// Each accumulator's lanes hold even-k / odd-k partial dots; summed at end.
// dist(k) = ||e_k||^2 - 2 * z.e_k   (z^2 term is constant per token)
// ---------------------------------------------------------------------------
__global__ void __launch_bounds__(256, 1)
argmin_kernel(const float* __restrict__ z, const float* __restrict__ cb) {
    extern __shared__ unsigned long long smem_u64[];
    unsigned long long* zs2 = smem_u64;                // [D2][BM]
    unsigned long long* es2 = smem_u64 + ZS_U64;       // [D2][BN]
    float* esq_s = reinterpret_cast<float*>(smem_u64 + ZS_U64 + ES_U64); // [K]

    const int tid = threadIdx.x;
    const int tx  = tid & 15;
    const int ty  = tid >> 4;
    const int m0  = blockIdx.x * BM;

    // Load z tile k-paired & transposed: zs2[k2][m] = (z[2k2], z[2k2+1])
    for (int i = tid; i < BM * (D / 4); i += 256) {
        int m  = i & (BM - 1);
        int d4 = i >> 6;                 // 0..63 -> covers k2 = 2*d4, 2*d4+1
        float4 v = *reinterpret_cast<const float4*>(z + (size_t)(m0 + m) * D + d4 * 4);
        float2 p0 = make_float2(v.x, v.y);
        float2 p1 = make_float2(v.z, v.w);
        zs2[(2 * d4 + 0) * BM + m] = *reinterpret_cast<unsigned long long*>(&p0);
        zs2[(2 * d4 + 1) * BM + m] = *reinterpret_cast<unsigned long long*>(&p1);
    }
    for (int i = tid; i < K; i += 256) esq_s[i] = g_esq[i];

    float bestD[TM];
    int   bestI[TM];
    #pragma unroll
    for (int mm = 0; mm < TM; ++mm) { bestD[mm] = FLT_MAX; bestI[mm] = 0; }

    for (int ch = 0; ch < NCHUNK; ++ch) {
        __syncthreads();  // prev compute done (and, 1st iter, zs2/esq stores done)
        const int c0 = ch * BN;
        // Load codebook chunk k-paired & transposed: es2[k2][c]
        for (int i = tid; i < BN * (D / 4); i += 256) {
            int c  = i & (BN - 1);
            int d4 = i >> 7;             // 0..63
            float4 v = *reinterpret_cast<const float4*>(cb + (size_t)(c0 + c) * D + d4 * 4);
            float2 p0 = make_float2(v.x, v.y);
            float2 p1 = make_float2(v.z, v.w);
            es2[(2 * d4 + 0) * BN + c] = *reinterpret_cast<unsigned long long*>(&p0);
            es2[(2 * d4 + 1) * BN + c] = *reinterpret_cast<unsigned long long*>(&p1);
        }
        __syncthreads();

        unsigned long long acc[TM][TN];
        #pragma unroll
        for (int mm = 0; mm < TM; ++mm)
            #pragma unroll
            for (int nn = 0; nn < TN; ++nn) acc[mm][nn] = 0ull;  // (0.f, 0.f)

        #pragma unroll 4
        for (int k2 = 0; k2 < D2; ++k2) {
            const ulonglong2 za = *reinterpret_cast<const ulonglong2*>(&zs2[k2 * BM + ty * TM]);
            const ulonglong2 zb = *reinterpret_cast<const ulonglong2*>(&zs2[k2 * BM + ty * TM + 2]);
            const ulonglong2 e0 = *reinterpret_cast<const ulonglong2*>(&es2[k2 * BN + tx * TN]);
            const ulonglong2 e1 = *reinterpret_cast<const ulonglong2*>(&es2[k2 * BN + tx * TN + 2]);
            const ulonglong2 e2 = *reinterpret_cast<const ulonglong2*>(&es2[k2 * BN + tx * TN + 4]);
            const ulonglong2 e3 = *reinterpret_cast<const ulonglong2*>(&es2[k2 * BN + tx * TN + 6]);
            const unsigned long long zp[TM] = {za.x, za.y, zb.x, zb.y};
            const unsigned long long ep[TN] = {e0.x, e0.y, e1.x, e1.y,
                                               e2.x, e2.y, e3.x, e3.y};
            #pragma unroll
            for (int mm = 0; mm < TM; ++mm)
                #pragma unroll
                for (int nn = 0; nn < TN; ++nn)
                    FMA_F32X2(acc[mm][nn], zp[mm], ep[nn]);
        }

        // Running argmin. Codes of this thread are ascending across (ch, nn),
        // so strict '<' keeps the earliest index on exact ties (jnp.argmin).
        #pragma unroll
        for (int mm = 0; mm < TM; ++mm) {
            #pragma unroll
            for (int nn = 0; nn < TN; ++nn) {
                float lo, hi;
                asm("mov.b64 {%0, %1}, %2;" : "=f"(lo), "=f"(hi) : "l"(acc[mm][nn]));
                float dot = lo + hi;
                int code = c0 + tx * TN + nn;
                float dist = esq_s[code] - 2.0f * dot;
                if (dist < bestD[mm]) { bestD[mm] = dist; bestI[mm] = code; }
            }
        }
    }

    // Cross-thread reduction over tx (16 candidates per token), reusing es2.
    __syncthreads();
    float* rd = reinterpret_cast<float*>(es2);   // [16][BM]
    int*   ri = reinterpret_cast<int*>(rd + 16 * BM);  // [16][BM]
    #pragma unroll
    for (int mm = 0; mm < TM; ++mm) {
        int m = ty * TM + mm;
        rd[tx * BM + m] = bestD[mm];
        ri[tx * BM + m] = bestI[mm];
    }
    __syncthreads();
    if (tid < BM) {
        float bd = rd[tid];
        int   bi = ri[tid];
        #pragma unroll
        for (int t = 1; t < 16; ++t) {
            float d2 = rd[t * BM + tid];
            int   i2 = ri[t * BM + tid];
            if (d2 < bd || (d2 == bd && i2 < bi)) { bd = d2; bi = i2; }
        }
        g_indices[m0 + tid] = bi;
    }
}

// ---------------------------------------------------------------------------
// Kernel 2: gather codebook rows, write quantized & indices, per-token loss
// mask read as 4-byte words: nonzero == true (covers int32 0/1 and f32 0/1)
// ---------------------------------------------------------------------------
__global__ void gather_kernel(const float* __restrict__ z,
                              const unsigned* __restrict__ mask,
                              const float* __restrict__ cb,
                              float* __restrict__ outQ,
                              float* __restrict__ outI) {
    const int t = blockIdx.x;
    const int d = threadIdx.x;          // 256 threads = D
    const int idx = g_indices[t];
    const unsigned mw = mask[t];

    const float zv = z[(size_t)t * D + d];
    const float ev = cb[(size_t)idx * D + d];
    outQ[(size_t)t * D + d] = mw ? ev : 0.0f;

    float diff = ev - zv;
    float s = diff * diff;
    #pragma unroll
    for (int o = 16; o > 0; o >>= 1) s += __shfl_down_sync(0xffffffffu, s, o);
    __shared__ float ws[8];
    if ((d & 31) == 0) ws[d >> 5] = s;
    __syncthreads();
    if (d == 0) {
        float tot = 0.f;
        #pragma unroll
        for (int w = 0; w < 8; ++w) tot += ws[w];
        g_partial[t] = tot;
        outI[t] = mw ? (float)idx : -1.0f;
    }
}

// ---------------------------------------------------------------------------
// Kernel 3a/3b: deterministic two-stage loss reduction (fixed order)
// ---------------------------------------------------------------------------
__global__ void loss1_kernel() {
    __shared__ float sm[256];
    const int tid = threadIdx.x;
    const int base = blockIdx.x * 256;
    sm[tid] = g_partial[base + tid];
    __syncthreads();
    #pragma unroll
    for (int s = 128; s > 0; s >>= 1) {
        if (tid < s) sm[tid] += sm[tid + s];
        __syncthreads();
    }
    if (tid == 0) g_partial2[blockIdx.x] = sm[0];
}

__global__ void loss2_kernel(float* __restrict__ outL) {
    __shared__ float sm[256];
    const int tid = threadIdx.x;
    sm[tid] = g_partial2[tid];
    __syncthreads();
    #pragma unroll
    for (int s = 128; s > 0; s >>= 1) {
        if (tid < s) sm[tid] += sm[tid + s];
        __syncthreads();
    }
    if (tid == 0)
        outL[0] = 0.25f * sm[0] / (float)((size_t)TOKENS * D);
}

// ---------------------------------------------------------------------------
extern "C" void kernel_launch(void* const* d_in, const int* in_sizes, int n_in,
                              void* d_out, int out_size) {
    const float*    z    = (const float*)d_in[0];
    const unsigned* mask = (const unsigned*)d_in[1];
    const float*    cb   = (const float*)d_in[2];

    float* out  = (float*)d_out;
    float* outQ = out;
    float* outI = out + (size_t)TOKENS * D;
    float* outL = outI + TOKENS;

    cudaFuncSetAttribute(argmin_kernel,
                         cudaFuncAttributeMaxDynamicSharedMemorySize,
                         (int)SMEM_BYTES);

    esq_kernel<<<K, D>>>(cb);
    argmin_kernel<<<TOKENS / BM, 256, SMEM_BYTES>>>(z, cb);
    gather_kernel<<<TOKENS, D>>>(z, mask, cb, outQ, outI);
    loss1_kernel<<<TOKENS / 256, 256>>>();
    loss2_kernel<<<1, 256>>>(outL);
}

// round 5
// speedup vs baseline: 2.7058x; 2.7058x over previous
#include <cuda_runtime.h>
#include <cstdint>
#include <cfloat>

// Problem constants (StyleCodebook: B=16, N=4096, D=256, K=512)
static constexpr int TOKENS = 65536;
static constexpr int D      = 256;   // GEMM K
static constexpr int K      = 512;   // codes = GEMM N

static constexpr int BM  = 128;      // tokens per CTA
static constexpr int BN  = 128;      // codes per N-chunk
static constexpr int KC  = 32;       // K-chunk (128B rows for SW128)
static constexpr int NKCH = D / KC;  // 8
static constexpr int NNCH = K / BN;  // 4

// dynamic smem layout (bytes)
static constexpr int SM_ESQ  = 0;                    // 512 f32
static constexpr int SM_AHI  = 2048;                 // 128 x 128B
static constexpr int SM_ALO  = SM_AHI + BM * 128;    // 18432
static constexpr int SM_BHI  = SM_ALO + BM * 128;    // 34816
static constexpr int SM_BLO  = SM_BHI + BN * 128;    // 51200
static constexpr int SMEM_TOTAL = SM_BLO + BN * 128; // 67584
// reduction scratch reuses B_HI after compute
static constexpr int SM_REDD = SM_BHI;               // 4*128 f32
static constexpr int SM_REDI = SM_BHI + 2048;        // 4*128 int

#define SWZ128(o) ((o) ^ ((((unsigned)(o)) >> 3) & 0x70))

// Scratch (device globals; no allocation allowed)
__device__ int   g_indices[TOKENS];
__device__ float g_partial[TOKENS];
__device__ float g_partial2[256];
__device__ float g_esq[K];

__device__ __forceinline__ uint32_t smem_u32(const void* p) {
    uint32_t a;
    asm("{ .reg .u64 t; cvta.to.shared.u64 t, %1; cvt.u32.u64 %0, t; }"
        : "=r"(a) : "l"(p));
    return a;
}

__device__ __forceinline__ float tf32_rn(float x) {
    uint32_t r;
    asm("cvt.rna.tf32.f32 %0, %1;" : "=r"(r) : "f"(x));
    return __uint_as_float(r);
}

#define LDSM_X4(r0, r1, r2, r3, addr)                                         \
    asm volatile(                                                             \
        "ldmatrix.sync.aligned.m8n8.x4.shared.b16 {%0,%1,%2,%3}, [%4];"       \
        : "=r"(r0), "=r"(r1), "=r"(r2), "=r"(r3) : "r"(addr))

#define MMA_TF32(d, a, b)                                                     \
    asm volatile(                                                             \
        "mma.sync.aligned.m16n8k8.row.col.f32.tf32.tf32.f32 "                 \
        "{%0,%1,%2,%3}, {%4,%5,%6,%7}, {%8,%9}, {%0,%1,%2,%3};"               \
        : "+f"((d)[0]), "+f"((d)[1]), "+f"((d)[2]), "+f"((d)[3])              \
        : "r"((a)[0]), "r"((a)[1]), "r"((a)[2]), "r"((a)[3]),                 \
          "r"((b)[0]), "r"((b)[1]))

// ---------------------------------------------------------------------------
// Kernel 0: codebook row squared norms
// ---------------------------------------------------------------------------
__global__ void esq_kernel(const float* __restrict__ cb) {
    int k = blockIdx.x;
    int d = threadIdx.x;
    float v = cb[(size_t)k * D + d];
    float s = v * v;
    #pragma unroll
    for (int o = 16; o > 0; o >>= 1) s += __shfl_down_sync(0xffffffffu, s, o);
    __shared__ float ws[8];
    if ((d & 31) == 0) ws[d >> 5] = s;
    __syncthreads();
    if (d == 0) {
        float tot = 0.f;
        #pragma unroll
        for (int w = 0; w < 8; ++w) tot += ws[w];
        g_esq[k] = tot;
    }
}

// ---------------------------------------------------------------------------
// Kernel 1: mma.sync tf32 (3xTF32 split) z@cb^T + fused argmin
// dist(k) = ||e_k||^2 - 2*dot  (z^2 constant per token)
// ---------------------------------------------------------------------------
__global__ void __launch_bounds__(256, 1)
argmin_mma_kernel(const float* __restrict__ z, const float* __restrict__ cb) {
    extern __shared__ char smem[];
    const uint32_t sb = smem_u32(smem);
    float* esq_s = reinterpret_cast<float*>(smem + SM_ESQ);

    const int tid   = threadIdx.x;
    const int lane  = tid & 31;
    const int warp  = tid >> 5;
    const int warpM = warp >> 2;           // 0..1 (64 rows each)
    const int warpN = warp & 3;            // 0..3 (32 cols each)
    const int m0    = blockIdx.x * BM;

    // ldmatrix per-lane geometry (same for A and B tiles)
    const int matIdx    = lane >> 3;
    const int rowInMat  = (lane & 7) + (matIdx & 1) * 8;  // 0..15 within 16-row tile
    const int segSel    = matIdx >> 1;                    // 0..1 (16B segs within k8)

    for (int i = tid; i < K; i += 256) esq_s[i] = g_esq[i];

    float bestD[8];
    int   bestI[8];
    #pragma unroll
    for (int b = 0; b < 8; ++b) { bestD[b] = FLT_MAX; bestI[b] = 0; }

    for (int nch = 0; nch < NNCH; ++nch) {
        float acc[4][4][4];
        #pragma unroll
        for (int mt = 0; mt < 4; ++mt)
            #pragma unroll
            for (int nt = 0; nt < 4; ++nt)
                #pragma unroll
                for (int r = 0; r < 4; ++r) acc[mt][nt][r] = 0.f;

        for (int kch = 0; kch < NKCH; ++kch) {
            __syncthreads();   // smem free (prev iter's ldmatrix done)
            const int k0 = kch * KC;

            // Stage A chunk: 128 rows x 32 f32 -> hi/lo, SW128
            #pragma unroll
            for (int j = 0; j < 4; ++j) {
                int i   = j * 256 + tid;
                int row = i >> 3, seg = i & 7;
                float4 v = *reinterpret_cast<const float4*>(
                    z + (size_t)(m0 + row) * D + k0 + seg * 4);
                float4 h, l;
                h.x = tf32_rn(v.x); l.x = tf32_rn(v.x - h.x);
                h.y = tf32_rn(v.y); l.y = tf32_rn(v.y - h.y);
                h.z = tf32_rn(v.z); l.z = tf32_rn(v.z - h.z);
                h.w = tf32_rn(v.w); l.w = tf32_rn(v.w - h.w);
                unsigned off = SWZ128(row * 128 + seg * 16);
                *reinterpret_cast<float4*>(smem + SM_AHI + off) = h;
                *reinterpret_cast<float4*>(smem + SM_ALO + off) = l;
            }
            // Stage B chunk: 128 code-rows x 32 f32 -> hi/lo, SW128
            #pragma unroll
            for (int j = 0; j < 4; ++j) {
                int i   = j * 256 + tid;
                int row = i >> 3, seg = i & 7;
                float4 v = *reinterpret_cast<const float4*>(
                    cb + (size_t)(nch * BN + row) * D + k0 + seg * 4);
                float4 h, l;
                h.x = tf32_rn(v.x); l.x = tf32_rn(v.x - h.x);
                h.y = tf32_rn(v.y); l.y = tf32_rn(v.y - h.y);
                h.z = tf32_rn(v.z); l.z = tf32_rn(v.z - h.z);
                h.w = tf32_rn(v.w); l.w = tf32_rn(v.w - h.w);
                unsigned off = SWZ128(row * 128 + seg * 16);
                *reinterpret_cast<float4*>(smem + SM_BHI + off) = h;
                *reinterpret_cast<float4*>(smem + SM_BLO + off) = l;
            }
            __syncthreads();

            #pragma unroll
            for (int kk = 0; kk < 4; ++kk) {
                const int seg = kk * 2 + segSel;  // 16B segment within row

                uint32_t ah[4][4], al[4][4];
                #pragma unroll
                for (int mt = 0; mt < 4; ++mt) {
                    int row = warpM * 64 + mt * 16 + rowInMat;
                    unsigned off = (unsigned)(row * 128 + ((seg ^ (row & 7)) << 4));
                    LDSM_X4(ah[mt][0], ah[mt][1], ah[mt][2], ah[mt][3],
                            sb + SM_AHI + off);
                    LDSM_X4(al[mt][0], al[mt][1], al[mt][2], al[mt][3],
                            sb + SM_ALO + off);
                }
                uint32_t bh[4][2], bl[4][2];
                #pragma unroll
                for (int p = 0; p < 2; ++p) {
                    int row = warpN * 32 + p * 16 + rowInMat;
                    unsigned off = (unsigned)(row * 128 + ((seg ^ (row & 7)) << 4));
                    uint32_t r0, r1, r2, r3;
                    LDSM_X4(r0, r1, r2, r3, sb + SM_BHI + off);
                    bh[2 * p][0] = r0; bh[2 * p][1] = r2;
                    bh[2 * p + 1][0] = r1; bh[2 * p + 1][1] = r3;
                    LDSM_X4(r0, r1, r2, r3, sb + SM_BLO + off);
                    bl[2 * p][0] = r0; bl[2 * p][1] = r2;
                    bl[2 * p + 1][0] = r1; bl[2 * p + 1][1] = r3;
                }
                #pragma unroll
                for (int mt = 0; mt < 4; ++mt)
                    #pragma unroll
                    for (int nt = 0; nt < 4; ++nt)
                        MMA_TF32(acc[mt][nt], ah[mt], bh[nt]);   // hi*hi
                #pragma unroll
                for (int mt = 0; mt < 4; ++mt)
                    #pragma unroll
                    for (int nt = 0; nt < 4; ++nt)
                        MMA_TF32(acc[mt][nt], ah[mt], bl[nt]);   // hi*lo
                #pragma unroll
                for (int mt = 0; mt < 4; ++mt)
                    #pragma unroll
                    for (int nt = 0; nt < 4; ++nt)
                        MMA_TF32(acc[mt][nt], al[mt], bh[nt]);   // lo*hi
            }
        }

        // Running argmin (codes ascending: nch, nt, col -> strict '<' keeps
        // the earliest index, matching jnp.argmin tie semantics)
        #pragma unroll
        for (int mt = 0; mt < 4; ++mt)
            #pragma unroll
            for (int half = 0; half < 2; ++half) {
                const int b = mt * 2 + half;
                #pragma unroll
                for (int nt = 0; nt < 4; ++nt) {
                    int code = nch * BN + warpN * 32 + nt * 8 + 2 * (lane & 3);
                    float d0 = esq_s[code]     - 2.f * acc[mt][nt][half * 2];
                    float d1 = esq_s[code + 1] - 2.f * acc[mt][nt][half * 2 + 1];
                    if (d0 < bestD[b]) { bestD[b] = d0; bestI[b] = code; }
                    if (d1 < bestD[b]) { bestD[b] = d1; bestI[b] = code + 1; }
                }
            }
    }

    // Quad reduction (threads in a quad share the same token row)
    #pragma unroll
    for (int b = 0; b < 8; ++b) {
        float d = bestD[b]; int i = bestI[b];
        #pragma unroll
        for (int off = 1; off < 4; off <<= 1) {
            float d2 = __shfl_xor_sync(0xffffffffu, d, off);
            int   i2 = __shfl_xor_sync(0xffffffffu, i, off);
            if (d2 < d || (d2 == d && i2 < i)) { d = d2; i = i2; }
        }
        bestD[b] = d; bestI[b] = i;
    }

    __syncthreads();   // compute done; reuse B_HI region
    float* redD = reinterpret_cast<float*>(smem + SM_REDD);
    int*   redI = reinterpret_cast<int*>(smem + SM_REDI);
    if ((lane & 3) == 0) {
        const int g = lane >> 2;
        #pragma unroll
        for (int mt = 0; mt < 4; ++mt)
            #pragma unroll
            for (int half = 0; half < 2; ++half) {
                int row = warpM * 64 + mt * 16 + half * 8 + g;
                redD[warpN * BM + row] = bestD[mt * 2 + half];
                redI[warpN * BM + row] = bestI[mt * 2 + half];
            }
    }
    __syncthreads();
    if (tid < BM) {
        float bd = redD[tid];
        int   bi = redI[tid];
        #pragma unroll
        for (int w = 1; w < 4; ++w) {
            float d2 = redD[w * BM + tid];
            int   i2 = redI[w * BM + tid];
            if (d2 < bd || (d2 == bd && i2 < bi)) { bd = d2; bi = i2; }
        }
        g_indices[m0 + tid] = bi;
    }
}

// ---------------------------------------------------------------------------
// Kernel 2: gather codebook rows, write quantized & indices, per-token loss
// ---------------------------------------------------------------------------
__global__ void gather_kernel(const float* __restrict__ z,
                              const unsigned* __restrict__ mask,
                              const float* __restrict__ cb,
                              float* __restrict__ outQ,
                              float* __restrict__ outI) {
    const int t = blockIdx.x;
    const int d = threadIdx.x;
    const int idx = g_indices[t];
    const unsigned mw = mask[t];

    const float zv = z[(size_t)t * D + d];
    const float ev = cb[(size_t)idx * D + d];
    outQ[(size_t)t * D + d] = mw ? ev : 0.0f;

    float diff = ev - zv;
    float s = diff * diff;
    #pragma unroll
    for (int o = 16; o > 0; o >>= 1) s += __shfl_down_sync(0xffffffffu, s, o);
    __shared__ float ws[8];
    if ((d & 31) == 0) ws[d >> 5] = s;
    __syncthreads();
    if (d == 0) {
        float tot = 0.f;
        #pragma unroll
        for (int w = 0; w < 8; ++w) tot += ws[w];
        g_partial[t] = tot;
        outI[t] = mw ? (float)idx : -1.0f;
    }
}

// ---------------------------------------------------------------------------
// Kernels 3a/3b: deterministic two-stage loss reduction
// ---------------------------------------------------------------------------
__global__ void loss1_kernel() {
    __shared__ float sm[256];
    const int tid = threadIdx.x;
    sm[tid] = g_partial[blockIdx.x * 256 + tid];
    __syncthreads();
    #pragma unroll
    for (int s = 128; s > 0; s >>= 1) {
        if (tid < s) sm[tid] += sm[tid + s];
        __syncthreads();
    }
    if (tid == 0) g_partial2[blockIdx.x] = sm[0];
}

__global__ void loss2_kernel(float* __restrict__ outL) {
    __shared__ float sm[256];
    const int tid = threadIdx.x;
    sm[tid] = g_partial2[tid];
    __syncthreads();
    #pragma unroll
    for (int s = 128; s > 0; s >>= 1) {
        if (tid < s) sm[tid] += sm[tid + s];
        __syncthreads();
    }
    if (tid == 0)
        outL[0] = 0.25f * sm[0] / (float)((size_t)TOKENS * D);
}

// ---------------------------------------------------------------------------
extern "C" void kernel_launch(void* const* d_in, const int* in_sizes, int n_in,
                              void* d_out, int out_size) {
    const float*    z    = (const float*)d_in[0];
    const unsigned* mask = (const unsigned*)d_in[1];
    const float*    cb   = (const float*)d_in[2];

    float* out  = (float*)d_out;
    float* outQ = out;
    float* outI = out + (size_t)TOKENS * D;
    float* outL = outI + TOKENS;

    cudaFuncSetAttribute(argmin_mma_kernel,
                         cudaFuncAttributeMaxDynamicSharedMemorySize, SMEM_TOTAL);

    esq_kernel<<<K, D>>>(cb);
    argmin_mma_kernel<<<TOKENS / BM, 256, SMEM_TOTAL>>>(z, cb);
    gather_kernel<<<TOKENS, D>>>(z, mask, cb, outQ, outI);
    loss1_kernel<<<TOKENS / 256, 256>>>();
    loss2_kernel<<<1, 256>>>(outL);
}

// round 6
// speedup vs baseline: 3.5663x; 1.3180x over previous
#include <cuda_runtime.h>
#include <cstdint>
#include <cfloat>

// Problem constants (StyleCodebook: B=16, N=4096, D=256, K=512)
static constexpr int TOKENS = 65536;
static constexpr int D      = 256;   // GEMM K
static constexpr int K      = 512;   // codes = GEMM N

static constexpr int BM  = 128;      // tokens per CTA
static constexpr int BN  = 128;      // codes per N-chunk
static constexpr int NKCH = 8;       // K-chunks of 32
static constexpr int NNCH = 4;       // N-chunks
static constexpr int NIT  = NKCH * NNCH;  // 32 pipeline iterations

// dynamic smem: esq | 2 stages x (A raw 16KB + B raw 16KB)
static constexpr int SM_ESQ = 0;
#define SM_A(s) (2048 + (s) * 32768)
#define SM_B(s) (SM_A(s) + 16384)
static constexpr int SMEM_TOTAL = 2048 + 2 * 32768;   // 67584
static constexpr int SM_REDD = SM_A(0);               // epilogue scratch
static constexpr int SM_REDI = SM_A(0) + 2048;

#define SWZ128(o) ((o) ^ ((((unsigned)(o)) >> 3) & 0x70))

// Scratch (device globals; no allocation allowed)
__device__ int   g_indices[TOKENS];
__device__ float g_partial[TOKENS];
__device__ float g_partial2[256];
__device__ float g_esq[K];

__device__ __forceinline__ uint32_t smem_u32(const void* p) {
    uint32_t a;
    asm("{ .reg .u64 t; cvta.to.shared.u64 t, %1; cvt.u32.u64 %0, t; }"
        : "=r"(a) : "l"(p));
    return a;
}

__device__ __forceinline__ float tf32_rn(float x) {
    uint32_t r;
    asm("cvt.rna.tf32.f32 %0, %1;" : "=r"(r) : "f"(x));
    return __uint_as_float(r);
}

#define CP_ASYNC16(dst, src)                                                  \
    asm volatile("cp.async.cg.shared.global [%0], [%1], 16;"                  \
                 :: "r"(dst), "l"(src))
#define CP_COMMIT() asm volatile("cp.async.commit_group;")
#define CP_WAIT(n)  asm volatile("cp.async.wait_group %0;" :: "n"(n))

#define LDSM_X4(r0, r1, r2, r3, addr)                                         \
    asm volatile(                                                             \
        "ldmatrix.sync.aligned.m8n8.x4.shared.b16 {%0,%1,%2,%3}, [%4];"       \
        : "=r"(r0), "=r"(r1), "=r"(r2), "=r"(r3) : "r"(addr))

#define MMA_TF32(d, a, b)                                                     \
    asm volatile(                                                             \
        "mma.sync.aligned.m16n8k8.row.col.f32.tf32.tf32.f32 "                 \
        "{%0,%1,%2,%3}, {%4,%5,%6,%7}, {%8,%9}, {%0,%1,%2,%3};"               \
        : "+f"((d)[0]), "+f"((d)[1]), "+f"((d)[2]), "+f"((d)[3])              \
        : "r"((a)[0]), "r"((a)[1]), "r"((a)[2]), "r"((a)[3]),                 \
          "r"((b)[0]), "r"((b)[1]))

// ---------------------------------------------------------------------------
// Kernel 0: codebook row squared norms
// ---------------------------------------------------------------------------
__global__ void esq_kernel(const float* __restrict__ cb) {
    int k = blockIdx.x;
    int d = threadIdx.x;
    float v = cb[(size_t)k * D + d];
    float s = v * v;
    #pragma unroll
    for (int o = 16; o > 0; o >>= 1) s += __shfl_down_sync(0xffffffffu, s, o);
    __shared__ float ws[8];
    if ((d & 31) == 0) ws[d >> 5] = s;
    __syncthreads();
    if (d == 0) {
        float tot = 0.f;
        #pragma unroll
        for (int w = 0; w < 8; ++w) tot += ws[w];
        g_esq[k] = tot;
    }
}

// ---------------------------------------------------------------------------
// cp.async staging of one (nch, kch) chunk into buffer it&1 (raw fp32)
// ---------------------------------------------------------------------------
__device__ __forceinline__ void stage_chunk(const float* __restrict__ z,
                                            const float* __restrict__ cb,
                                            uint32_t sb, int tid, int it, int m0) {
    const int nch = it >> 3, kch = it & 7, buf = it & 1;
    const uint32_t aB = sb + SM_A(buf);
    const uint32_t bB = sb + SM_B(buf);
    #pragma unroll
    for (int j = 0; j < 4; ++j) {
        int i   = j * 256 + tid;
        int row = i >> 3, seg = i & 7;
        unsigned off = SWZ128(row * 128 + seg * 16);
        const float* sA = z + (size_t)(m0 + row) * D + kch * 32 + seg * 4;
        CP_ASYNC16(aB + off, (size_t)__cvta_generic_to_global(sA));
        const float* sB = cb + (size_t)(nch * BN + row) * D + kch * 32 + seg * 4;
        CP_ASYNC16(bB + off, (size_t)__cvta_generic_to_global(sB));
    }
}

// ---------------------------------------------------------------------------
// Compute one chunk: ldmatrix raw fp32 frags, split hi/lo in regs, 3xTF32 MMA
// ---------------------------------------------------------------------------
__device__ __forceinline__ void compute_chunk(uint32_t aBase, uint32_t bBase,
                                              float (&acc)[4][4][4],
                                              int warpM, int warpN,
                                              int rowInMat, int segSel) {
    #pragma unroll
    for (int kk = 0; kk < 4; ++kk) {
        const int seg = kk * 2 + segSel;

        uint32_t ahf[4][4], alf[4][4];
        #pragma unroll
        for (int mt = 0; mt < 4; ++mt) {
            int row = warpM * 64 + mt * 16 + rowInMat;
            unsigned off = (unsigned)(row * 128 + ((seg ^ (row & 7)) << 4));
            uint32_t r0, r1, r2, r3;
            LDSM_X4(r0, r1, r2, r3, aBase + off);
            uint32_t raw[4] = {r0, r1, r2, r3};
            #pragma unroll
            for (int q = 0; q < 4; ++q) {
                float v = __uint_as_float(raw[q]);
                float h = tf32_rn(v);
                ahf[mt][q] = __float_as_uint(h);
                alf[mt][q] = __float_as_uint(tf32_rn(v - h));
            }
        }

        uint32_t bhf[4][2], blf[4][2];
        #pragma unroll
        for (int p = 0; p < 2; ++p) {
            int row = warpN * 32 + p * 16 + rowInMat;
            unsigned off = (unsigned)(row * 128 + ((seg ^ (row & 7)) << 4));
            uint32_t r0, r1, r2, r3;
            LDSM_X4(r0, r1, r2, r3, bBase + off);
            // fragment mapping: bh[2p]={r0,r2}, bh[2p+1]={r1,r3}
            uint32_t raw[4] = {r0, r2, r1, r3};
            #pragma unroll
            for (int q = 0; q < 4; ++q) {
                float v = __uint_as_float(raw[q]);
                float h = tf32_rn(v);
                bhf[2 * p + (q >> 1)][q & 1] = __float_as_uint(h);
                blf[2 * p + (q >> 1)][q & 1] = __float_as_uint(tf32_rn(v - h));
            }
        }

        #pragma unroll
        for (int mt = 0; mt < 4; ++mt)
            #pragma unroll
            for (int nt = 0; nt < 4; ++nt)
                MMA_TF32(acc[mt][nt], ahf[mt], bhf[nt]);   // hi*hi
        #pragma unroll
        for (int mt = 0; mt < 4; ++mt)
            #pragma unroll
            for (int nt = 0; nt < 4; ++nt)
                MMA_TF32(acc[mt][nt], ahf[mt], blf[nt]);   // hi*lo
        #pragma unroll
        for (int mt = 0; mt < 4; ++mt)
            #pragma unroll
            for (int nt = 0; nt < 4; ++nt)
                MMA_TF32(acc[mt][nt], alf[mt], bhf[nt]);   // lo*hi
    }
}

// ---------------------------------------------------------------------------
// Kernel 1: pipelined mma.sync tf32 z@cb^T + fused argmin
// dist(k) = ||e_k||^2 - 2*dot  (z^2 constant per token)
// ---------------------------------------------------------------------------
__global__ void __launch_bounds__(256, 1)
argmin_mma_kernel(const float* __restrict__ z, const float* __restrict__ cb) {
    extern __shared__ char smem[];
    const uint32_t sb = smem_u32(smem);
    float* esq_s = reinterpret_cast<float*>(smem + SM_ESQ);

    const int tid   = threadIdx.x;
    const int lane  = tid & 31;
    const int warp  = tid >> 5;
    const int warpM = warp >> 2;
    const int warpN = warp & 3;
    const int m0    = blockIdx.x * BM;

    const int matIdx   = lane >> 3;
    const int rowInMat = (lane & 7) + (matIdx & 1) * 8;
    const int segSel   = matIdx >> 1;

    for (int i = tid; i < K; i += 256) esq_s[i] = g_esq[i];

    float bestD[8];
    int   bestI[8];
    #pragma unroll
    for (int b = 0; b < 8; ++b) { bestD[b] = FLT_MAX; bestI[b] = 0; }

    // Pipeline prologue: stages 0, 1 in flight
    stage_chunk(z, cb, sb, tid, 0, m0); CP_COMMIT();
    stage_chunk(z, cb, sb, tid, 1, m0); CP_COMMIT();

    for (int nch = 0; nch < NNCH; ++nch) {
        float acc[4][4][4];
        #pragma unroll
        for (int mt = 0; mt < 4; ++mt)
            #pragma unroll
            for (int nt = 0; nt < 4; ++nt)
                #pragma unroll
                for (int r = 0; r < 4; ++r) acc[mt][nt][r] = 0.f;

        for (int kch = 0; kch < NKCH; ++kch) {
            const int it = nch * NKCH + kch;
            if (it == NIT - 1) { CP_WAIT(0); } else { CP_WAIT(1); }
            __syncthreads();                    // chunk it visible to all
            const int buf = it & 1;
            compute_chunk(sb + SM_A(buf), sb + SM_B(buf), acc,
                          warpM, warpN, rowInMat, segSel);
            __syncthreads();                    // all done reading buf
            if (it + 2 < NIT) {
                stage_chunk(z, cb, sb, tid, it + 2, m0);
                CP_COMMIT();
            }
        }

        // Running argmin (codes ascending across nch/nt/col: strict '<'
        // keeps the earliest index, matching jnp.argmin tie semantics)
        #pragma unroll
        for (int mt = 0; mt < 4; ++mt)
            #pragma unroll
            for (int half = 0; half < 2; ++half) {
                const int b = mt * 2 + half;
                #pragma unroll
                for (int nt = 0; nt < 4; ++nt) {
                    int code = nch * BN + warpN * 32 + nt * 8 + 2 * (lane & 3);
                    float d0 = esq_s[code]     - 2.f * acc[mt][nt][half * 2];
                    float d1 = esq_s[code + 1] - 2.f * acc[mt][nt][half * 2 + 1];
                    if (d0 < bestD[b]) { bestD[b] = d0; bestI[b] = code; }
                    if (d1 < bestD[b]) { bestD[b] = d1; bestI[b] = code + 1; }
                }
            }
    }

    // Quad reduction (threads in a quad share the same token row)
    #pragma unroll
    for (int b = 0; b < 8; ++b) {
        float d = bestD[b]; int i = bestI[b];
        #pragma unroll
        for (int off = 1; off < 4; off <<= 1) {
            float d2 = __shfl_xor_sync(0xffffffffu, d, off);
            int   i2 = __shfl_xor_sync(0xffffffffu, i, off);
            if (d2 < d || (d2 == d && i2 < i)) { d = d2; i = i2; }
        }
        bestD[b] = d; bestI[b] = i;
    }

    __syncthreads();   // compute done; reuse pipeline smem
    float* redD = reinterpret_cast<float*>(smem + SM_REDD);
    int*   redI = reinterpret_cast<int*>(smem + SM_REDI);
    if ((lane & 3) == 0) {
        const int g = lane >> 2;
        #pragma unroll
        for (int mt = 0; mt < 4; ++mt)
            #pragma unroll
            for (int half = 0; half < 2; ++half) {
                int row = warpM * 64 + mt * 16 + half * 8 + g;
                redD[warpN * BM + row] = bestD[mt * 2 + half];
                redI[warpN * BM + row] = bestI[mt * 2 + half];
            }
    }
    __syncthreads();
    if (tid < BM) {
        float bd = redD[tid];
        int   bi = redI[tid];
        #pragma unroll
        for (int w = 1; w < 4; ++w) {
            float d2 = redD[w * BM + tid];
            int   i2 = redI[w * BM + tid];
            if (d2 < bd || (d2 == bd && i2 < bi)) { bd = d2; bi = i2; }
        }
        g_indices[m0 + tid] = bi;
    }
}

// ---------------------------------------------------------------------------
// Kernel 2: warp-per-token gather + masked writes + per-token loss partial
// ---------------------------------------------------------------------------
__global__ void __launch_bounds__(256)
gather_kernel(const float* __restrict__ z,
              const unsigned* __restrict__ mask,
              const float* __restrict__ cb,
              float* __restrict__ outQ,
              float* __restrict__ outI) {
    const int t    = blockIdx.x * 8 + (threadIdx.x >> 5);
    const int lane = threadIdx.x & 31;
    const int idx  = g_indices[t];
    const unsigned mw = mask[t];

    const float4* zr = reinterpret_cast<const float4*>(z  + (size_t)t   * D) + lane * 2;
    const float4* er = reinterpret_cast<const float4*>(cb + (size_t)idx * D) + lane * 2;
    float4 z0 = zr[0], z1 = zr[1];
    float4 e0 = er[0], e1 = er[1];

    float4* qw = reinterpret_cast<float4*>(outQ + (size_t)t * D) + lane * 2;
    const float4 zero4 = make_float4(0.f, 0.f, 0.f, 0.f);
    qw[0] = mw ? e0 : zero4;
    qw[1] = mw ? e1 : zero4;

    float s = 0.f;
    float d;
    d = e0.x - z0.x; s += d * d;  d = e0.y - z0.y; s += d * d;
    d = e0.z - z0.z; s += d * d;  d = e0.w - z0.w; s += d * d;
    d = e1.x - z1.x; s += d * d;  d = e1.y - z1.y; s += d * d;
    d = e1.z - z1.z; s += d * d;  d = e1.w - z1.w; s += d * d;
    #pragma unroll
    for (int o = 16; o > 0; o >>= 1) s += __shfl_down_sync(0xffffffffu, s, o);
    if (lane == 0) {
        g_partial[t] = s;
        outI[t] = mw ? (float)idx : -1.0f;
    }
}

// ---------------------------------------------------------------------------
// Kernels 3a/3b: deterministic two-stage loss reduction
// ---------------------------------------------------------------------------
__global__ void loss1_kernel() {
    __shared__ float sm[256];
    const int tid = threadIdx.x;
    sm[tid] = g_partial[blockIdx.x * 256 + tid];
    __syncthreads();
    #pragma unroll
    for (int s = 128; s > 0; s >>= 1) {
        if (tid < s) sm[tid] += sm[tid + s];
        __syncthreads();
    }
    if (tid == 0) g_partial2[blockIdx.x] = sm[0];
}

__global__ void loss2_kernel(float* __restrict__ outL) {
    __shared__ float sm[256];
    const int tid = threadIdx.x;
    sm[tid] = g_partial2[tid];
    __syncthreads();
    #pragma unroll
    for (int s = 128; s > 0; s >>= 1) {
        if (tid < s) sm[tid] += sm[tid + s];
        __syncthreads();
    }
    if (tid == 0)
        outL[0] = 0.25f * sm[0] / (float)((size_t)TOKENS * D);
}

// ---------------------------------------------------------------------------
extern "C" void kernel_launch(void* const* d_in, const int* in_sizes, int n_in,
                              void* d_out, int out_size) {
    const float*    z    = (const float*)d_in[0];
    const unsigned* mask = (const unsigned*)d_in[1];
    const float*    cb   = (const float*)d_in[2];

    float* out  = (float*)d_out;
    float* outQ = out;
    float* outI = out + (size_t)TOKENS * D;
    float* outL = outI + TOKENS;

    cudaFuncSetAttribute(argmin_mma_kernel,
                         cudaFuncAttributeMaxDynamicSharedMemorySize, SMEM_TOTAL);

    esq_kernel<<<K, D>>>(cb);
    argmin_mma_kernel<<<TOKENS / BM, 256, SMEM_TOTAL>>>(z, cb);
    gather_kernel<<<TOKENS / 8, 256>>>(z, mask, cb, outQ, outI);
    loss1_kernel<<<TOKENS / 256, 256>>>();
    loss2_kernel<<<1, 256>>>(outL);
}

// round 7
// speedup vs baseline: 3.7416x; 1.0492x over previous
#include <cuda_runtime.h>
#include <cstdint>
#include <cfloat>

// Problem constants (StyleCodebook: B=16, N=4096, D=256, K=512)
static constexpr int TOKENS = 65536;
static constexpr int D      = 256;   // GEMM K
static constexpr int K      = 512;   // codes = GEMM N

static constexpr int BM  = 128;      // tokens per CTA
static constexpr int BN  = 128;      // codes per N-chunk
static constexpr int NKCH = 8;       // K-chunks of 32
static constexpr int NNCH = 4;       // N-chunks
static constexpr int NIT  = NKCH * NNCH;  // 32 pipeline iterations
static constexpr int STG  = 3;       // pipeline stages

// dynamic smem: esq | 3 stages x (A raw 16KB + B raw 16KB)
static constexpr int SM_ESQ = 0;
#define SM_A(s) (2048 + (s) * 32768)
#define SM_B(s) (SM_A(s) + 16384)
static constexpr int SMEM_TOTAL = 2048 + STG * 32768;  // 100352
static constexpr int SM_REDD = SM_A(0);                // epilogue scratch
static constexpr int SM_REDI = SM_A(0) + 2048;

#define SWZ128(o) ((o) ^ ((((unsigned)(o)) >> 3) & 0x70))

// Scratch (device globals; no allocation allowed)
__device__ int   g_indices[TOKENS];
__device__ float g_partial2[TOKENS / 8];   // one partial per gather CTA
__device__ float g_esq[K];

__device__ __forceinline__ uint32_t smem_u32(const void* p) {
    uint32_t a;
    asm("{ .reg .u64 t; cvta.to.shared.u64 t, %1; cvt.u32.u64 %0, t; }"
        : "=r"(a) : "l"(p));
    return a;
}

__device__ __forceinline__ float tf32_rn(float x) {
    uint32_t r;
    asm("cvt.rna.tf32.f32 %0, %1;" : "=r"(r) : "f"(x));
    return __uint_as_float(r);
}

#define CP_ASYNC16(dst, src)                                                  \
    asm volatile("cp.async.cg.shared.global [%0], [%1], 16;"                  \
                 :: "r"(dst), "l"(src))
#define CP_COMMIT() asm volatile("cp.async.commit_group;")
#define CP_WAIT(n)  asm volatile("cp.async.wait_group %0;" :: "n"(n))

#define LDSM_X4(r0, r1, r2, r3, addr)                                         \
    asm volatile(                                                             \
        "ldmatrix.sync.aligned.m8n8.x4.shared.b16 {%0,%1,%2,%3}, [%4];"       \
        : "=r"(r0), "=r"(r1), "=r"(r2), "=r"(r3) : "r"(addr))

#define MMA_TF32(d, a, b)                                                     \
    asm volatile(                                                             \
        "mma.sync.aligned.m16n8k8.row.col.f32.tf32.tf32.f32 "                 \
        "{%0,%1,%2,%3}, {%4,%5,%6,%7}, {%8,%9}, {%0,%1,%2,%3};"               \
        : "+f"((d)[0]), "+f"((d)[1]), "+f"((d)[2]), "+f"((d)[3])              \
        : "r"((a)[0]), "r"((a)[1]), "r"((a)[2]), "r"((a)[3]),                 \
          "r"((b)[0]), "r"((b)[1]))

// ---------------------------------------------------------------------------
// Kernel 0: codebook row squared norms
// ---------------------------------------------------------------------------
__global__ void esq_kernel(const float* __restrict__ cb) {
    int k = blockIdx.x;
    int d = threadIdx.x;
    float v = cb[(size_t)k * D + d];
    float s = v * v;
    #pragma unroll
    for (int o = 16; o > 0; o >>= 1) s += __shfl_down_sync(0xffffffffu, s, o);
    __shared__ float ws[8];
    if ((d & 31) == 0) ws[d >> 5] = s;
    __syncthreads();
    if (d == 0) {
        float tot = 0.f;
        #pragma unroll
        for (int w = 0; w < 8; ++w) tot += ws[w];
        g_esq[k] = tot;
    }
}

// ---------------------------------------------------------------------------
// cp.async staging of one (nch, kch) chunk into buffer it%STG (raw fp32)
// ---------------------------------------------------------------------------
__device__ __forceinline__ void stage_chunk(const float* __restrict__ z,
                                            const float* __restrict__ cb,
                                            uint32_t sb, int tid, int it, int m0) {
    const int nch = it >> 3, kch = it & 7, buf = it % STG;
    const uint32_t aB = sb + SM_A(buf);
    const uint32_t bB = sb + SM_B(buf);
    #pragma unroll
    for (int j = 0; j < 4; ++j) {
        int i   = j * 256 + tid;
        int row = i >> 3, seg = i & 7;
        unsigned off = SWZ128(row * 128 + seg * 16);
        const float* sA = z + (size_t)(m0 + row) * D + kch * 32 + seg * 4;
        CP_ASYNC16(aB + off, (size_t)__cvta_generic_to_global(sA));
        const float* sB = cb + (size_t)(nch * BN + row) * D + kch * 32 + seg * 4;
        CP_ASYNC16(bB + off, (size_t)__cvta_generic_to_global(sB));
    }
}

// ---------------------------------------------------------------------------
// Compute one chunk: ldmatrix raw fp32 frags, split hi/lo in regs, 3xTF32 MMA.
// lo operands are passed raw (v - h): the tf32 MMA truncates them in HW; the
// truncation error is <= 2^-22 relative, below the split's own error floor.
// ---------------------------------------------------------------------------
__device__ __forceinline__ void compute_chunk(uint32_t aBase, uint32_t bBase,
                                              float (&acc)[4][4][4],
                                              int warpM, int warpN,
                                              int rowInMat, int segSel) {
    #pragma unroll
    for (int kk = 0; kk < 4; ++kk) {
        const int seg = kk * 2 + segSel;

        uint32_t ahf[4][4], alf[4][4];
        #pragma unroll
        for (int mt = 0; mt < 4; ++mt) {
            int row = warpM * 64 + mt * 16 + rowInMat;
            unsigned off = (unsigned)(row * 128 + ((seg ^ (row & 7)) << 4));
            uint32_t r0, r1, r2, r3;
            LDSM_X4(r0, r1, r2, r3, aBase + off);
            uint32_t raw[4] = {r0, r1, r2, r3};
            #pragma unroll
            for (int q = 0; q < 4; ++q) {
                float v = __uint_as_float(raw[q]);
                float h = tf32_rn(v);
                ahf[mt][q] = __float_as_uint(h);
                alf[mt][q] = __float_as_uint(v - h);   // raw lo, HW-truncated
            }
        }

        uint32_t bhf[4][2], blf[4][2];
        #pragma unroll
        for (int p = 0; p < 2; ++p) {
            int row = warpN * 32 + p * 16 + rowInMat;
            unsigned off = (unsigned)(row * 128 + ((seg ^ (row & 7)) << 4));
            uint32_t r0, r1, r2, r3;
            LDSM_X4(r0, r1, r2, r3, bBase + off);
            // fragment mapping: bh[2p]={r0,r2}, bh[2p+1]={r1,r3}
            uint32_t raw[4] = {r0, r2, r1, r3};
            #pragma unroll
            for (int q = 0; q < 4; ++q) {
                float v = __uint_as_float(raw[q]);
                float h = tf32_rn(v);
                bhf[2 * p + (q >> 1)][q & 1] = __float_as_uint(h);
                blf[2 * p + (q >> 1)][q & 1] = __float_as_uint(v - h);
            }
        }

        #pragma unroll
        for (int mt = 0; mt < 4; ++mt)
            #pragma unroll
            for (int nt = 0; nt < 4; ++nt)
                MMA_TF32(acc[mt][nt], ahf[mt], bhf[nt]);   // hi*hi
        #pragma unroll
        for (int mt = 0; mt < 4; ++mt)
            #pragma unroll
            for (int nt = 0; nt < 4; ++nt)
                MMA_TF32(acc[mt][nt], ahf[mt], blf[nt]);   // hi*lo
        #pragma unroll
        for (int mt = 0; mt < 4; ++mt)
            #pragma unroll
            for (int nt = 0; nt < 4; ++nt)
                MMA_TF32(acc[mt][nt], alf[mt], bhf[nt]);   // lo*hi
    }
}

// ---------------------------------------------------------------------------
// Kernel 1: 3-stage pipelined mma.sync tf32 z@cb^T + fused argmin
// dist(k) = ||e_k||^2 - 2*dot  (z^2 constant per token)
// ---------------------------------------------------------------------------
__global__ void __launch_bounds__(256, 1)
argmin_mma_kernel(const float* __restrict__ z, const float* __restrict__ cb) {
    extern __shared__ char smem[];
    const uint32_t sb = smem_u32(smem);
    float* esq_s = reinterpret_cast<float*>(smem + SM_ESQ);

    const int tid   = threadIdx.x;
    const int lane  = tid & 31;
    const int warp  = tid >> 5;
    const int warpM = warp >> 2;
    const int warpN = warp & 3;
    const int m0    = blockIdx.x * BM;

    const int matIdx   = lane >> 3;
    const int rowInMat = (lane & 7) + (matIdx & 1) * 8;
    const int segSel   = matIdx >> 1;

    for (int i = tid; i < K; i += 256) esq_s[i] = g_esq[i];

    float bestD[8];
    int   bestI[8];
    #pragma unroll
    for (int b = 0; b < 8; ++b) { bestD[b] = FLT_MAX; bestI[b] = 0; }

    // Pipeline prologue: chunks 0, 1 in flight
    stage_chunk(z, cb, sb, tid, 0, m0); CP_COMMIT();
    stage_chunk(z, cb, sb, tid, 1, m0); CP_COMMIT();

    for (int nch = 0; nch < NNCH; ++nch) {
        float acc[4][4][4];
        #pragma unroll
        for (int mt = 0; mt < 4; ++mt)
            #pragma unroll
            for (int nt = 0; nt < 4; ++nt)
                #pragma unroll
                for (int r = 0; r < 4; ++r) acc[mt][nt][r] = 0.f;

        for (int kch = 0; kch < NKCH; ++kch) {
            const int it = nch * NKCH + kch;
            // Buffer (it+2)%3 was last READ at iteration it-1; this barrier
            // separates those reads from the new cp.async writes below.
            if (it == NIT - 1) { CP_WAIT(0); } else { CP_WAIT(1); }
            __syncthreads();
            if (it + 2 < NIT) {
                stage_chunk(z, cb, sb, tid, it + 2, m0);
                CP_COMMIT();
            }
            compute_chunk(sb + SM_A(it % STG), sb + SM_B(it % STG), acc,
                          warpM, warpN, rowInMat, segSel);
        }

        // Running argmin (codes ascending across nch/nt/col: strict '<'
        // keeps the earliest index, matching jnp.argmin tie semantics)
        #pragma unroll
        for (int mt = 0; mt < 4; ++mt)
            #pragma unroll
            for (int half = 0; half < 2; ++half) {
                const int b = mt * 2 + half;
                #pragma unroll
                for (int nt = 0; nt < 4; ++nt) {
                    int code = nch * BN + warpN * 32 + nt * 8 + 2 * (lane & 3);
                    float d0 = esq_s[code]     - 2.f * acc[mt][nt][half * 2];
                    float d1 = esq_s[code + 1] - 2.f * acc[mt][nt][half * 2 + 1];
                    if (d0 < bestD[b]) { bestD[b] = d0; bestI[b] = code; }
                    if (d1 < bestD[b]) { bestD[b] = d1; bestI[b] = code + 1; }
                }
            }
    }

    // Quad reduction (threads in a quad share the same token row)
    #pragma unroll
    for (int b = 0; b < 8; ++b) {
        float d = bestD[b]; int i = bestI[b];
        #pragma unroll
        for (int off = 1; off < 4; off <<= 1) {
            float d2 = __shfl_xor_sync(0xffffffffu, d, off);
            int   i2 = __shfl_xor_sync(0xffffffffu, i, off);
            if (d2 < d || (d2 == d && i2 < i)) { d = d2; i = i2; }
        }
        bestD[b] = d; bestI[b] = i;
    }

    __syncthreads();   // compute done; reuse pipeline smem
    float* redD = reinterpret_cast<float*>(smem + SM_REDD);
    int*   redI = reinterpret_cast<int*>(smem + SM_REDI);
    if ((lane & 3) == 0) {
        const int g = lane >> 2;
        #pragma unroll
        for (int mt = 0; mt < 4; ++mt)
            #pragma unroll
            for (int half = 0; half < 2; ++half) {
                int row = warpM * 64 + mt * 16 + half * 8 + g;
                redD[warpN * BM + row] = bestD[mt * 2 + half];
                redI[warpN * BM + row] = bestI[mt * 2 + half];
            }
    }
    __syncthreads();
    if (tid < BM) {
        float bd = redD[tid];
        int   bi = redI[tid];
        #pragma unroll
        for (int w = 1; w < 4; ++w) {
            float d2 = redD[w * BM + tid];
            int   i2 = redI[w * BM + tid];
            if (d2 < bd || (d2 == bd && i2 < bi)) { bd = d2; bi = i2; }
        }
        g_indices[m0 + tid] = bi;
    }
}

// ---------------------------------------------------------------------------
// Kernel 2: warp-per-token gather + masked writes + per-CTA loss partial
// ---------------------------------------------------------------------------
__global__ void __launch_bounds__(256)
gather_kernel(const float* __restrict__ z,
              const unsigned* __restrict__ mask,
              const float* __restrict__ cb,
              float* __restrict__ outQ,
              float* __restrict__ outI) {
    const int warp = threadIdx.x >> 5;
    const int lane = threadIdx.x & 31;
    const int t    = blockIdx.x * 8 + warp;
    const int idx  = g_indices[t];
    const unsigned mw = mask[t];

    const float4* zr = reinterpret_cast<const float4*>(z  + (size_t)t   * D) + lane * 2;
    const float4* er = reinterpret_cast<const float4*>(cb + (size_t)idx * D) + lane * 2;
    float4 z0 = zr[0], z1 = zr[1];
    float4 e0 = er[0], e1 = er[1];

    float4* qw = reinterpret_cast<float4*>(outQ + (size_t)t * D) + lane * 2;
    const float4 zero4 = make_float4(0.f, 0.f, 0.f, 0.f);
    qw[0] = mw ? e0 : zero4;
    qw[1] = mw ? e1 : zero4;

    float s = 0.f;
    float d;
    d = e0.x - z0.x; s += d * d;  d = e0.y - z0.y; s += d * d;
    d = e0.z - z0.z; s += d * d;  d = e0.w - z0.w; s += d * d;
    d = e1.x - z1.x; s += d * d;  d = e1.y - z1.y; s += d * d;
    d = e1.z - z1.z; s += d * d;  d = e1.w - z1.w; s += d * d;
    #pragma unroll
    for (int o = 16; o > 0; o >>= 1) s += __shfl_down_sync(0xffffffffu, s, o);

    __shared__ float ws[8];
    if (lane == 0) {
        ws[warp] = s;
        outI[t] = mw ? (float)idx : -1.0f;
    }
    __syncthreads();
    if (threadIdx.x == 0) {
        float tot = 0.f;
        #pragma unroll
        for (int w = 0; w < 8; ++w) tot += ws[w];
        g_partial2[blockIdx.x] = tot;
    }
}

// ---------------------------------------------------------------------------
// Kernel 3: deterministic final loss reduction over 8192 partials
// ---------------------------------------------------------------------------
__global__ void loss_kernel(float* __restrict__ outL) {
    __shared__ float sm[256];
    const int tid = threadIdx.x;
    float a = 0.f;
    #pragma unroll
    for (int j = 0; j < 32; ++j) a += g_partial2[tid * 32 + j];  // fixed order
    sm[tid] = a;
    __syncthreads();
    #pragma unroll
    for (int s = 128; s > 0; s >>= 1) {
        if (tid < s) sm[tid] += sm[tid + s];
        __syncthreads();
    }
    if (tid == 0)
        outL[0] = 0.25f * sm[0] / (float)((size_t)TOKENS * D);
}

// ---------------------------------------------------------------------------
extern "C" void kernel_launch(void* const* d_in, const int* in_sizes, int n_in,
                              void* d_out, int out_size) {
    const float*    z    = (const float*)d_in[0];
    const unsigned* mask = (const unsigned*)d_in[1];
    const float*    cb   = (const float*)d_in[2];

    float* out  = (float*)d_out;
    float* outQ = out;
    float* outI = out + (size_t)TOKENS * D;
    float* outL = outI + TOKENS;

    cudaFuncSetAttribute(argmin_mma_kernel,
                         cudaFuncAttributeMaxDynamicSharedMemorySize, SMEM_TOTAL);

    esq_kernel<<<K, D>>>(cb);
    argmin_mma_kernel<<<TOKENS / BM, 256, SMEM_TOTAL>>>(z, cb);
    gather_kernel<<<TOKENS / 8, 256>>>(z, mask, cb, outQ, outI);
    loss_kernel<<<1, 256>>>(outL);
}